// round 1
// baseline (speedup 1.0000x reference)
#include <cuda_runtime.h>
#include <math.h>

#define FRAMES 32
#define FRAME_ELEMS (720*1280)          // 921600
#define TOTAL_ELEMS (FRAMES*FRAME_ELEMS)
#define NB (1<<20)                      // histogram bins
#define CHUNKS 1024
#define BPF 225                         // blocks per frame: 225*256*16 = 921600
#define TPB 256

struct Stats {
    double sum_p[FRAMES];
    double sum_p2[FRAMES];
    double sum_fp[FRAMES];
    double cnt_fix[FRAMES];
    double sum_sim[FRAMES];
    double sum_g;
    unsigned pmin_enc, pmax_enc, gmin_enc, gmax_enc;
    int bstar;
    unsigned long long u1, u2, u3;
    // finalized values
    float pminf, gminf, bin_scale;
    float invTpf, invTgf;
};

__device__ Stats g_s;
__device__ unsigned g_hf[NB];
__device__ unsigned g_hn[NB];
__device__ unsigned g_chunkF[CHUNKS];
__device__ unsigned g_chunkFpre[CHUNKS];

// ---------- helpers ----------
__device__ __forceinline__ unsigned encF(float x) {
    unsigned u = __float_as_uint(x);
    return (u & 0x80000000u) ? ~u : (u | 0x80000000u);
}
__device__ __forceinline__ float decF(unsigned u) {
    u = (u & 0x80000000u) ? (u & 0x7FFFFFFFu) : ~u;
    return __uint_as_float(u);
}

__device__ __forceinline__ double blkSumD(double v, double* sh) {
    #pragma unroll
    for (int o = 16; o; o >>= 1) v += __shfl_down_sync(0xFFFFFFFFu, v, o);
    if ((threadIdx.x & 31) == 0) sh[threadIdx.x >> 5] = v;
    __syncthreads();
    double r = 0.0;
    if (threadIdx.x < 32) {
        r = (threadIdx.x < 8) ? sh[threadIdx.x] : 0.0;
        #pragma unroll
        for (int o = 4; o; o >>= 1) r += __shfl_down_sync(0xFFFFFFFFu, r, o);
    }
    __syncthreads();
    return r;   // valid on thread 0
}

__device__ __forceinline__ float blkMinF(float v, float* sh) {
    #pragma unroll
    for (int o = 16; o; o >>= 1) v = fminf(v, __shfl_down_sync(0xFFFFFFFFu, v, o));
    if ((threadIdx.x & 31) == 0) sh[threadIdx.x >> 5] = v;
    __syncthreads();
    float r = 3.4e38f;
    if (threadIdx.x < 32) {
        r = (threadIdx.x < 8) ? sh[threadIdx.x] : 3.4e38f;
        #pragma unroll
        for (int o = 4; o; o >>= 1) r = fminf(r, __shfl_down_sync(0xFFFFFFFFu, r, o));
    }
    __syncthreads();
    return r;
}

__device__ __forceinline__ float blkMaxF(float v, float* sh) {
    #pragma unroll
    for (int o = 16; o; o >>= 1) v = fmaxf(v, __shfl_down_sync(0xFFFFFFFFu, v, o));
    if ((threadIdx.x & 31) == 0) sh[threadIdx.x >> 5] = v;
    __syncthreads();
    float r = -3.4e38f;
    if (threadIdx.x < 32) {
        r = (threadIdx.x < 8) ? sh[threadIdx.x] : -3.4e38f;
        #pragma unroll
        for (int o = 4; o; o >>= 1) r = fmaxf(r, __shfl_down_sync(0xFFFFFFFFu, r, o));
    }
    __syncthreads();
    return r;
}

__device__ __forceinline__ unsigned long long blkSumU(unsigned long long v, unsigned long long* sh) {
    #pragma unroll
    for (int o = 16; o; o >>= 1) v += __shfl_down_sync(0xFFFFFFFFu, v, o);
    if ((threadIdx.x & 31) == 0) sh[threadIdx.x >> 5] = v;
    __syncthreads();
    unsigned long long r = 0;
    if (threadIdx.x < 32) {
        r = (threadIdx.x < 8) ? sh[threadIdx.x] : 0ull;
        #pragma unroll
        for (int o = 4; o; o >>= 1) r += __shfl_down_sync(0xFFFFFFFFu, r, o);
    }
    __syncthreads();
    return r;
}

// ---------- kernels ----------
__global__ void k_zero() {
    int i = blockIdx.x * blockDim.x + threadIdx.x;
    int stride = gridDim.x * blockDim.x;
    for (int b = i; b < NB; b += stride) { g_hf[b] = 0u; g_hn[b] = 0u; }
}

__global__ void k_init() {
    int t = threadIdx.x;
    if (t < FRAMES) {
        g_s.sum_p[t] = 0.0; g_s.sum_p2[t] = 0.0; g_s.sum_fp[t] = 0.0;
        g_s.cnt_fix[t] = 0.0; g_s.sum_sim[t] = 0.0;
    }
    if (t == 0) {
        g_s.sum_g = 0.0;
        g_s.pmin_enc = 0xFFFFFFFFu; g_s.pmax_enc = 0u;
        g_s.gmin_enc = 0xFFFFFFFFu; g_s.gmax_enc = 0u;
        g_s.bstar = NB;
        g_s.u1 = 0ull; g_s.u2 = 0ull; g_s.u3 = 0ull;
    }
}

// Pass 1: per-frame NSS stats + global min/max/sums
__global__ void k_main(const float* __restrict__ pred, const float* __restrict__ gt,
                       const int* __restrict__ fix) {
    __shared__ double shd[8];
    __shared__ float shf[8];
    int f = blockIdx.y;
    size_t base = (size_t)f * FRAME_ELEMS + (size_t)blockIdx.x * 4096u;
    const float4* p4 = reinterpret_cast<const float4*>(pred + base);
    const float4* g4 = reinterpret_cast<const float4*>(gt + base);
    const int4*   x4 = reinterpret_cast<const int4*>(fix + base);

    float sp = 0.f, sp2 = 0.f, sfp = 0.f, sg = 0.f, cf = 0.f;
    float pmn = 3.4e38f, pmx = -3.4e38f, gmn = 3.4e38f, gmx = -3.4e38f;
    #pragma unroll
    for (int k = 0; k < 4; k++) {
        int i = threadIdx.x + 256 * k;
        float4 p = p4[i]; float4 g = g4[i]; int4 x = x4[i];
        sp  += (p.x + p.y) + (p.z + p.w);
        sp2 += (p.x*p.x + p.y*p.y) + (p.z*p.z + p.w*p.w);
        sg  += (g.x + g.y) + (g.z + g.w);
        pmn = fminf(pmn, fminf(fminf(p.x, p.y), fminf(p.z, p.w)));
        pmx = fmaxf(pmx, fmaxf(fmaxf(p.x, p.y), fmaxf(p.z, p.w)));
        gmn = fminf(gmn, fminf(fminf(g.x, g.y), fminf(g.z, g.w)));
        gmx = fmaxf(gmx, fmaxf(fmaxf(g.x, g.y), fmaxf(g.z, g.w)));
        if (x.x) { sfp += p.x; cf += 1.f; }
        if (x.y) { sfp += p.y; cf += 1.f; }
        if (x.z) { sfp += p.z; cf += 1.f; }
        if (x.w) { sfp += p.w; cf += 1.f; }
    }
    double rs  = blkSumD((double)sp,  shd);
    double rs2 = blkSumD((double)sp2, shd);
    double rfp = blkSumD((double)sfp, shd);
    double rg  = blkSumD((double)sg,  shd);
    double rcf = blkSumD((double)cf,  shd);
    float rpmn = blkMinF(pmn, shf);
    float rpmx = blkMaxF(pmx, shf);
    float rgmn = blkMinF(gmn, shf);
    float rgmx = blkMaxF(gmx, shf);
    if (threadIdx.x == 0) {
        atomicAdd(&g_s.sum_p[f],  rs);
        atomicAdd(&g_s.sum_p2[f], rs2);
        atomicAdd(&g_s.sum_fp[f], rfp);
        atomicAdd(&g_s.cnt_fix[f], rcf);
        atomicAdd(&g_s.sum_g,     rg);
        atomicMin(&g_s.pmin_enc, encF(rpmn));
        atomicMax(&g_s.pmax_enc, encF(rpmx));
        atomicMin(&g_s.gmin_enc, encF(rgmn));
        atomicMax(&g_s.gmax_enc, encF(rgmx));
    }
}

__global__ void k_finalize() {
    float pmin = decF(g_s.pmin_enc), pmax = decF(g_s.pmax_enc);
    float gmin = decF(g_s.gmin_enc);
    double sumP = 0.0;
    for (int f = 0; f < FRAMES; f++) sumP += g_s.sum_p[f];
    double Tp = sumP - (double)TOTAL_ELEMS * (double)pmin;
    double Tg = g_s.sum_g - (double)TOTAL_ELEMS * (double)gmin;
    g_s.pminf = pmin; g_s.gminf = gmin;
    g_s.invTpf = (float)(1.0 / Tp);
    g_s.invTgf = (float)(1.0 / Tg);
    g_s.bin_scale = (float)((double)NB / ((double)pmax - (double)pmin));
}

// Pass 2: SIM  (needs global min/max + totals)
__global__ void k_sim(const float* __restrict__ pred, const float* __restrict__ gt) {
    __shared__ double shd[8];
    int f = blockIdx.y;
    size_t base = (size_t)f * FRAME_ELEMS + (size_t)blockIdx.x * 4096u;
    const float4* p4 = reinterpret_cast<const float4*>(pred + base);
    const float4* g4 = reinterpret_cast<const float4*>(gt + base);
    float pmin = g_s.pminf, gmin = g_s.gminf, ip = g_s.invTpf, ig = g_s.invTgf;
    float acc = 0.f;
    #pragma unroll
    for (int k = 0; k < 4; k++) {
        int i = threadIdx.x + 256 * k;
        float4 p = p4[i]; float4 g = g4[i];
        if (g.x > gmin) acc += fminf((g.x - gmin) * ig, (p.x - pmin) * ip);
        if (g.y > gmin) acc += fminf((g.y - gmin) * ig, (p.y - pmin) * ip);
        if (g.z > gmin) acc += fminf((g.z - gmin) * ig, (p.z - pmin) * ip);
        if (g.w > gmin) acc += fminf((g.w - gmin) * ig, (p.w - pmin) * ip);
    }
    double r = blkSumD((double)acc, shd);
    if (threadIdx.x == 0) atomicAdd(&g_s.sum_sim[f], r);
}

// AUC: histogram of frame-0 pred split by fixation
__global__ void k_hist(const float* __restrict__ pred, const int* __restrict__ fix) {
    float pmin = g_s.pminf, scale = g_s.bin_scale;
    size_t base = (size_t)blockIdx.x * 4096u;
    const float4* p4 = reinterpret_cast<const float4*>(pred + base);
    const int4*   x4 = reinterpret_cast<const int4*>(fix + base);
    #pragma unroll
    for (int k = 0; k < 4; k++) {
        int i = threadIdx.x + 256 * k;
        float4 p = p4[i]; int4 x = x4[i];
        int b0 = min(NB - 1, (int)((p.x - pmin) * scale));
        int b1 = min(NB - 1, (int)((p.y - pmin) * scale));
        int b2 = min(NB - 1, (int)((p.z - pmin) * scale));
        int b3 = min(NB - 1, (int)((p.w - pmin) * scale));
        atomicAdd(x.x ? &g_hf[b0] : &g_hn[b0], 1u);
        atomicAdd(x.y ? &g_hf[b1] : &g_hn[b1], 1u);
        atomicAdd(x.z ? &g_hf[b2] : &g_hn[b2], 1u);
        atomicAdd(x.w ? &g_hf[b3] : &g_hn[b3], 1u);
    }
}

// chunk sums of H_fix + lowest fixation bin (bstar)
__global__ void k_chunksum() {
    __shared__ unsigned shu[8];
    __shared__ int shm[8];
    int c = blockIdx.x, t = threadIdx.x;
    unsigned sum = 0; int mn = NB;
    #pragma unroll
    for (int k = 0; k < 4; k++) {
        int b = c * 1024 + t + 256 * k;
        unsigned v = g_hf[b];
        sum += v;
        if (v && b < mn) mn = b;
    }
    #pragma unroll
    for (int o = 16; o; o >>= 1) {
        sum += __shfl_down_sync(0xFFFFFFFFu, sum, o);
        mn = min(mn, __shfl_down_sync(0xFFFFFFFFu, mn, o));
    }
    if ((t & 31) == 0) { shu[t >> 5] = sum; shm[t >> 5] = mn; }
    __syncthreads();
    if (t < 32) {
        unsigned s2 = (t < 8) ? shu[t] : 0u;
        int m2 = (t < 8) ? shm[t] : NB;
        #pragma unroll
        for (int o = 4; o; o >>= 1) {
            s2 += __shfl_down_sync(0xFFFFFFFFu, s2, o);
            m2 = min(m2, __shfl_down_sync(0xFFFFFFFFu, m2, o));
        }
        if (t == 0) {
            g_chunkF[c] = s2;
            if (m2 < NB) atomicMin(&g_s.bstar, m2);
        }
    }
}

// exclusive prefix over the 1024 chunk sums
__global__ void k_scanchunks() {
    __shared__ unsigned s[1024];
    int t = threadIdx.x;
    unsigned v = g_chunkF[t];
    s[t] = v;
    __syncthreads();
    for (int o = 1; o < 1024; o <<= 1) {
        unsigned a = (t >= o) ? s[t - o] : 0u;
        __syncthreads();
        s[t] += a;
        __syncthreads();
    }
    g_chunkFpre[t] = s[t] - v;
}

// compute U terms: u1 = Σ Hn·Fpre, u2 = Σ Hf·Hn, u3 = Σ_{b>bstar} Hn
__global__ void k_u() {
    __shared__ unsigned s[256];
    __shared__ unsigned long long shu[8];
    int c = blockIdx.x, t = threadIdx.x;
    int base = c * 1024 + t * 4;
    uint4 hf = *reinterpret_cast<const uint4*>(&g_hf[base]);
    uint4 hn = *reinterpret_cast<const uint4*>(&g_hn[base]);
    unsigned local = hf.x + hf.y + hf.z + hf.w;
    s[t] = local;
    __syncthreads();
    for (int o = 1; o < 256; o <<= 1) {
        unsigned a = (t >= o) ? s[t - o] : 0u;
        __syncthreads();
        s[t] += a;
        __syncthreads();
    }
    unsigned F = g_chunkFpre[c] + s[t] - local;
    int bstar = g_s.bstar;
    unsigned long long u1 = 0, u2 = 0, u3 = 0;
    u1 += (unsigned long long)hn.x * F; u2 += (unsigned long long)hf.x * hn.x; if (base + 0 > bstar) u3 += hn.x; F += hf.x;
    u1 += (unsigned long long)hn.y * F; u2 += (unsigned long long)hf.y * hn.y; if (base + 1 > bstar) u3 += hn.y; F += hf.y;
    u1 += (unsigned long long)hn.z * F; u2 += (unsigned long long)hf.z * hn.z; if (base + 2 > bstar) u3 += hn.z; F += hf.z;
    u1 += (unsigned long long)hn.w * F; u2 += (unsigned long long)hf.w * hn.w; if (base + 3 > bstar) u3 += hn.w; F += hf.w;
    u1 = blkSumU(u1, shu);
    u2 = blkSumU(u2, shu);
    u3 = blkSumU(u3, shu);
    if (t == 0) {
        atomicAdd(&g_s.u1, u1);
        atomicAdd(&g_s.u2, u2);
        atomicAdd(&g_s.u3, u3);
    }
}

__global__ void k_final(float* out) {
    double Np = (double)FRAME_ELEMS;
    double Nf = g_s.cnt_fix[0];
    double D  = Np - Nf;
    double S  = (double)g_s.u1 + 0.5 * (double)g_s.u2;
    double b  = (double)g_s.u3;
    double auc = ((2.0 * Nf + 1.0) * b + 1.0 - 2.0 * S) / (2.0 * Nf * D)
               + 1.0 - (b + 1.0) / D;
    double sim = 0.0, nss = 0.0;
    for (int f = 0; f < FRAMES; f++) {
        sim += g_s.sum_sim[f];
        double m   = g_s.sum_p[f] / Np;
        double var = g_s.sum_p2[f] / Np - m * m;
        double sd  = sqrt(var);
        double c   = g_s.cnt_fix[f];
        nss += (g_s.sum_fp[f] - c * m) / (sd * c);
    }
    sim /= (double)FRAMES;
    nss /= (double)FRAMES;
    double loss = auc + sim + nss;
    out[0] = (float)loss;
    out[1] = (float)auc;
    out[2] = (float)sim;
    out[3] = (float)nss;
}

extern "C" void kernel_launch(void* const* d_in, const int* in_sizes, int n_in,
                              void* d_out, int out_size) {
    const float* pred = (const float*)d_in[0];
    const float* gt   = (const float*)d_in[1];
    const int*   fix  = (const int*)d_in[2];
    float* out = (float*)d_out;

    k_zero<<<2048, 256>>>();
    k_init<<<1, 64>>>();
    dim3 gfull(BPF, FRAMES);
    k_main<<<gfull, TPB>>>(pred, gt, fix);
    k_finalize<<<1, 1>>>();
    k_sim<<<gfull, TPB>>>(pred, gt);
    k_hist<<<BPF, TPB>>>(pred, fix);
    k_chunksum<<<CHUNKS, 256>>>();
    k_scanchunks<<<1, 1024>>>();
    k_u<<<CHUNKS, 256>>>();
    k_final<<<1, 1>>>(out);
}